// round 4
// baseline (speedup 1.0000x reference)
#include <cuda_runtime.h>
#include <cuda_bf16.h>
#include <cstdint>
#include <cstddef>

// diag[h][t], h in [0,4), t in [0,16)
__device__ float g_diag[64];
// Wo converted to bf16, [o][k] row-major, 256x256
__device__ __nv_bfloat16 g_wo[65536];

// ---------------------------------------------------------------------------
// Kernel 1: merged prep. Blocks 0..3: attention softmax diagonal (one head
// each, low-register design). Blocks 4..67: Wo fp32 -> bf16 conversion.
// ---------------------------------------------------------------------------
__global__ void prep_kernel(const float* __restrict__ x, const float* __restrict__ y,
                            const float* __restrict__ Wq, const float* __restrict__ bq,
                            const float* __restrict__ Wk, const float* __restrict__ bk,
                            const float* __restrict__ Wo)
{
    const int tid = threadIdx.x;
    if (blockIdx.x >= 4) {
        // Wo conversion: 64 blocks x 256 threads x 4 elems
        const int i = (blockIdx.x - 4) * 1024 + tid * 4;
        const float4 v = *reinterpret_cast<const float4*>(Wo + i);
        __nv_bfloat16 o[4] = { __float2bfloat16(v.x), __float2bfloat16(v.y),
                               __float2bfloat16(v.z), __float2bfloat16(v.w) };
        *reinterpret_cast<uint64_t*>(g_wo + i) = *reinterpret_cast<uint64_t*>(o);
        return;
    }

    __shared__ float xs[4096], ys[4096];
    __shared__ float qs[1024];      // [t][cl]
    __shared__ float ks2[16 * 68];  // [t][cl] padded stride 68
    __shared__ float sc[256];
    const int h = blockIdx.x;

    for (int i = tid; i < 4096; i += 256) { xs[i] = x[i]; ys[i] = y[i]; }
    __syncthreads();

    // thread = (tg, cl): computes q[t][cl], k[t][cl] for t = tg*4..tg*4+3
    const int cl = tid & 63;
    const int tg = tid >> 6;
    const int c  = h * 64 + cl;
    const float* wqr = Wq + (size_t)c * 256;
    const float* wkr = Wk + (size_t)c * 256;
    float aq[4] = {0.f, 0.f, 0.f, 0.f}, ak[4] = {0.f, 0.f, 0.f, 0.f};
    #pragma unroll 4
    for (int m = 0; m < 256; ++m) {
        const float wq = wqr[m], wk = wkr[m];
        #pragma unroll
        for (int tt = 0; tt < 4; ++tt) {
            aq[tt] += xs[(tg * 4 + tt) * 256 + m] * wq;
            ak[tt] += ys[(tg * 4 + tt) * 256 + m] * wk;
        }
    }
    #pragma unroll
    for (int tt = 0; tt < 4; ++tt) {
        qs[(tg * 4 + tt) * 64 + cl]  = aq[tt] + bq[c];
        ks2[(tg * 4 + tt) * 68 + cl] = ak[tt] + bk[c];
    }
    __syncthreads();
    {
        const int i = tid >> 4, j = tid & 15;
        float s = 0.f;
        #pragma unroll 8
        for (int d = 0; d < 64; ++d) s += qs[i * 64 + d] * ks2[j * 68 + d];
        sc[tid] = s * 0.125f;
    }
    __syncthreads();
    if (tid < 16) {
        float mx = -1e30f;
        for (int j = 0; j < 16; ++j) mx = fmaxf(mx, sc[tid * 16 + j]);
        float sum = 0.f;
        for (int j = 0; j < 16; ++j) sum += expf(sc[tid * 16 + j] - mx);
        g_diag[h * 16 + tid] = expf(sc[tid * 16 + tid] - mx) / sum;
    }
}

// ---------------------------------------------------------------------------
// Kernel 2: fused permuted-gather bf16 GEMM + epilogue (no staging buffer).
// Per CTA (t, b, o0, ab, w0): D[o(128), n(128)] over K=256, 4 chunks of 64.
//   k = 4*dl + jj ; n = al*16 + wl
//   B[k][n] = z[t, b*64 + kc*16 + dl, w0+wl, ab + jj*32 + al]
// z loaded via LDG.32 (4 along wl) -> cvt bf16 -> STS.64 into swizzled tile.
// Granule (16B) = 8 consecutive wl at fixed al -> fragment cols are w-adjacent.
// ---------------------------------------------------------------------------
#define SMEM_BYTES 65536   // 2x16KB A + 2x16KB B

__device__ __forceinline__ void cp16(uint32_t dst, const void* src)
{
    asm volatile("cp.async.cg.shared.global [%0], [%1], 16;" :: "r"(dst), "l"(src));
}

__global__ void __launch_bounds__(256, 2)
fuse_kernel(const float* __restrict__ z, const float* __restrict__ bo,
            float* __restrict__ out)
{
    extern __shared__ char smem[];

    const int tid = threadIdx.x;
    const int bid = blockIdx.x;
    const int t   = bid >> 8;              // t-major for L2 reuse of z[t]
    const int b   = (bid >> 6) & 3;
    const int o0  = ((bid >> 5) & 1) << 7;
    const int ab  = ((bid >> 3) & 3) << 3;
    const int w0  = (bid & 7) << 4;

    const float* zslab = z + (size_t)(t * 256 + b * 64) * 16384 + (size_t)w0 * 128 + ab;

    const uint32_t abuf_s = (uint32_t)__cvta_generic_to_shared(smem);
    const uint32_t bbuf_s = abuf_s + 32768;

    // ---- A tile fill: g_wo bf16 -> swizzled smem via cp.async ----
    auto fillA = [&](int kc, int buf) {
        const uint32_t base = abuf_s + buf * 16384;
        const __nv_bfloat16* wsrc = g_wo + (size_t)o0 * 256 + kc * 64;
        #pragma unroll
        for (int i = 0; i < 4; ++i) {
            const int L = tid + i * 256;
            const int row = L >> 3, g = L & 7;
            cp16(base + (uint32_t)(row * 128 + ((g ^ (row & 7)) * 16)),
                 wsrc + row * 256 + g * 8);
        }
    };

    // ---- B prefetch: 8 units of (k, al, wl4), 4 LDG.32 along wl each ----
    // unit U = tid + i*256: al = U&7, wl4 = (U>>3)&3, k = U>>5
    float pre[8][4];
    auto issueLDG = [&](int kc) {
        #pragma unroll
        for (int i = 0; i < 8; ++i) {
            const int U   = tid + i * 256;
            const int al  = U & 7;
            const int wl4 = (U >> 3) & 3;
            const int k   = U >> 5;
            const int dl  = k >> 2, jj = k & 3;
            const float* src = zslab + (size_t)(kc * 16 + dl) * 16384
                             + (size_t)(wl4 * 4) * 128 + jj * 32 + al;
            #pragma unroll
            for (int r = 0; r < 4; ++r) pre[i][r] = src[r * 128];
        }
    };
    // ---- convert + STS into swizzled B tile ----
    auto storeB = [&](int buf) {
        const uint32_t base = bbuf_s + buf * 16384;
        #pragma unroll
        for (int i = 0; i < 8; ++i) {
            const int U   = tid + i * 256;
            const int al  = U & 7;
            const int wl4 = (U >> 3) & 3;
            const int k   = U >> 5;
            uint32_t p0, p1;
            asm("cvt.rn.bf16x2.f32 %0, %1, %2;" : "=r"(p0) : "f"(pre[i][1]), "f"(pre[i][0]));
            asm("cvt.rn.bf16x2.f32 %0, %1, %2;" : "=r"(p1) : "f"(pre[i][3]), "f"(pre[i][2]));
            const int gn   = al * 2 + (wl4 >> 1);
            const int phys = (gn & 8) | ((gn ^ (k & 7)) & 7);
            const uint32_t dst = base + (uint32_t)(k * 256 + phys * 16 + (wl4 & 1) * 8);
            asm volatile("st.shared.v2.b32 [%0], {%1,%2};" :: "r"(dst), "r"(p0), "r"(p1));
        }
    };

    const int lane = tid & 31;
    const int wrp  = tid >> 5;
    const int wm   = (wrp & 1) * 64;
    const int wn   = (wrp >> 1) * 32;
    const int grp  = lane >> 2;
    const int qid  = lane & 3;
    const int l16  = lane & 15;
    const int lhi  = lane >> 4;

    float acc[4][4][4];
    #pragma unroll
    for (int i = 0; i < 4; ++i)
        #pragma unroll
        for (int j = 0; j < 4; ++j)
            #pragma unroll
            for (int r = 0; r < 4; ++r) acc[i][j][r] = 0.f;

    // ---- prologue ----
    issueLDG(0);
    fillA(0, 0);
    asm volatile("cp.async.commit_group;");
    storeB(0);                 // waits on LDG(0) data
    issueLDG(1);
    fillA(1, 1);
    asm volatile("cp.async.commit_group;");
    asm volatile("cp.async.wait_group 1;");   // A0 landed
    __syncthreads();

    #pragma unroll 1
    for (int kc = 0; kc < 4; ++kc) {
        const int cur = kc & 1;
        const uint32_t abase = abuf_s + cur * 16384;
        const uint32_t bbase = bbuf_s + cur * 16384;

        #pragma unroll
        for (int ks = 0; ks < 4; ++ks) {
            uint32_t afr[4][4];
            #pragma unroll
            for (int mt = 0; mt < 4; ++mt) {
                const int row = wm + mt * 16 + l16;
                const int g   = (2 * ks + lhi) ^ (row & 7);
                const uint32_t addr = abase + (uint32_t)(row * 128 + g * 16);
                asm volatile("ldmatrix.sync.aligned.m8n8.x4.shared.b16 {%0,%1,%2,%3}, [%4];"
                             : "=r"(afr[mt][0]), "=r"(afr[mt][1]),
                               "=r"(afr[mt][2]), "=r"(afr[mt][3])
                             : "r"(addr));
            }
            uint32_t bfr[4][2];
            #pragma unroll
            for (int p = 0; p < 2; ++p) {
                const int k  = ks * 16 + l16;
                const int gn = ((wn >> 3) + 2 * p + lhi) ^ (k & 7);
                const uint32_t addr = bbase + (uint32_t)(k * 256 + gn * 16);
                asm volatile("ldmatrix.sync.aligned.m8n8.x4.trans.shared.b16 {%0,%1,%2,%3}, [%4];"
                             : "=r"(bfr[2*p][0]), "=r"(bfr[2*p][1]),
                               "=r"(bfr[2*p+1][0]), "=r"(bfr[2*p+1][1])
                             : "r"(addr));
            }
            #pragma unroll
            for (int mt = 0; mt < 4; ++mt)
                #pragma unroll
                for (int nt = 0; nt < 4; ++nt) {
                    asm volatile(
                        "mma.sync.aligned.m16n8k16.row.col.f32.bf16.bf16.f32 "
                        "{%0,%1,%2,%3}, {%4,%5,%6,%7}, {%8,%9}, {%0,%1,%2,%3};"
                        : "+f"(acc[mt][nt][0]), "+f"(acc[mt][nt][1]),
                          "+f"(acc[mt][nt][2]), "+f"(acc[mt][nt][3])
                        : "r"(afr[mt][0]), "r"(afr[mt][1]),
                          "r"(afr[mt][2]), "r"(afr[mt][3]),
                          "r"(bfr[nt][0]), "r"(bfr[nt][1]));
                }
        }

        if (kc < 3) {
            storeB(cur ^ 1);                         // chunk kc+1 (regs from last issue)
            asm volatile("cp.async.wait_group 0;");  // A[kc+1] landed
            __syncthreads();
            if (kc < 2) {
                issueLDG(kc + 2);                    // hidden under next compute
                fillA(kc + 2, cur);
                asm volatile("cp.async.commit_group;");
            }
        }
    }

    // ---- Epilogue: out = bo + z + diag * acc ; float2 stores along w ----
    const float dg = g_diag[b * 16 + t];
    #pragma unroll
    for (int mt = 0; mt < 4; ++mt) {
        #pragma unroll
        for (int half = 0; half < 2; ++half) {
            const int o = o0 + wm + mt * 16 + grp + half * 8;
            const float bov = bo[o];
            const size_t obase = (size_t)(t * 256 + o) * 16384;
            #pragma unroll
            for (int nt = 0; nt < 4; ++nt) {
                const int ncol = wn + nt * 8 + 2 * qid;   // even; pair in same al
                const int al = ncol >> 4;
                const int wl = ncol & 15;
                const int hp = (ab + al) * 4 + b;
                const size_t off = obase + (size_t)hp * 128 + (w0 + wl);
                const float2 zr = *reinterpret_cast<const float2*>(z + off);
                float2 r;
                r.x = bov + zr.x + dg * acc[mt][nt][half * 2 + 0];
                r.y = bov + zr.y + dg * acc[mt][nt][half * 2 + 1];
                *reinterpret_cast<float2*>(out + off) = r;
            }
        }
    }
}

// ---------------------------------------------------------------------------
extern "C" void kernel_launch(void* const* d_in, const int* in_sizes, int n_in,
                              void* d_out, int out_size)
{
    (void)in_sizes; (void)n_in; (void)out_size;
    const float* x  = (const float*)d_in[0];
    const float* y  = (const float*)d_in[1];
    const float* z  = (const float*)d_in[2];
    const float* Wq = (const float*)d_in[3];
    const float* bq = (const float*)d_in[4];
    const float* Wk = (const float*)d_in[5];
    const float* bk = (const float*)d_in[6];
    const float* Wo = (const float*)d_in[7];
    const float* bo = (const float*)d_in[8];
    float* out = (float*)d_out;

    cudaFuncSetAttribute(fuse_kernel, cudaFuncAttributeMaxDynamicSharedMemorySize,
                         SMEM_BYTES);

    prep_kernel<<<68, 256>>>(x, y, Wq, bq, Wk, bk, Wo);
    fuse_kernel<<<4096, 256, SMEM_BYTES>>>(z, bo, out);
}